// round 1
// baseline (speedup 1.0000x reference)
#include <cuda_runtime.h>
#include <math.h>

#define BB 16
#define TD 392
#define CD 512
#define E8D 64
#define KD 196
#define TT (TD*TD)          // 153664
#define NCHUNK 444
#define KSTEPS_TOTAL (TT/32) // 4802
#define SPB 11               // ceil(4802/444)

// ---- scratch (device globals; no allocation allowed) ----
__device__ __align__(16) float g_xi [BB*TD*E8D];     // 1.6 MB
__device__ __align__(16) float g_att[BB*TT];         // 9.8 MB
__device__ __align__(16) float g_part[NCHUNK*BB*TD]; // 11.1 MB
__device__ __align__(16) float g_xt [BB*TD];
__device__ int   g_i0[2*BB*KD];
__device__ int   g_i1[2*BB*KD];
__device__ float g_w1[2*BB*KD];

// ============================================================
// Kernel 1: xi[b,t,e] = x[b,t,:] . W_dim[e,:] + b_dim[e]
// block tile 32t x 64e, K-chunk 32, 128 threads, 4x4 reg tile
// ============================================================
__global__ void k_xi(const float* __restrict__ x,
                     const float* __restrict__ Wd,
                     const float* __restrict__ bd)
{
    __shared__ float xs[32*33];
    __shared__ float ws[64*33];
    const int b  = blockIdx.y;
    const int t0 = blockIdx.x * 32;
    const int tid = threadIdx.x;
    const int tx = tid & 15;   // e group (16 groups x 4)
    const int ty = tid >> 4;   // t group (8 groups x 4)

    float acc[4][4];
#pragma unroll
    for (int j=0;j<4;j++)
#pragma unroll
        for (int i=0;i<4;i++) acc[j][i] = 0.f;

    for (int s=0; s<CD/32; s++){
        const int k0 = s*32;
        __syncthreads();
        for (int g=tid; g<32*32; g+=128){
            int tt = g>>5, kk = g&31;
            int t = t0+tt;
            xs[tt*33+kk] = (t<TD) ? x[((size_t)b*TD+t)*CD + k0+kk] : 0.f;
        }
        for (int g=tid; g<64*32; g+=128){
            int ee = g>>5, kk = g&31;
            ws[ee*33+kk] = Wd[ee*CD + k0+kk];
        }
        __syncthreads();
#pragma unroll
        for (int kk=0;kk<32;kk++){
            float xv[4], wv[4];
#pragma unroll
            for (int j=0;j<4;j++) xv[j] = xs[(ty+8*j)*33+kk];
#pragma unroll
            for (int i=0;i<4;i++) wv[i] = ws[(tx+16*i)*33+kk];
#pragma unroll
            for (int j=0;j<4;j++)
#pragma unroll
                for (int i=0;i<4;i++) acc[j][i] += xv[j]*wv[i];
        }
    }
#pragma unroll
    for (int j=0;j<4;j++){
        int t = t0 + ty + 8*j;
        if (t < TD){
#pragma unroll
            for (int i=0;i<4;i++){
                int e = tx + 16*i;
                g_xi[((size_t)b*TD+t)*E8D + e] = acc[j][i] + bd[e];
            }
        }
    }
}

// ============================================================
// Kernel 2: att[b,i,:] = softmax_j( xi_i . xi_j / 512 )
// block = (b, 14-row i-tile), scores staged in shared
// ============================================================
__global__ void k_att()
{
    __shared__ __align__(16) float xs_i[14*E8D];  // 3.5 KB
    __shared__ float sc[14*TD];                   // 21.4 KB
    const int b  = blockIdx.y;
    const int i0 = blockIdx.x * 14;
    const int tid = threadIdx.x;   // 256

    const float* base = g_xi + ((size_t)b*TD + i0)*E8D;
    for (int g=tid; g<14*E8D; g+=256) xs_i[g] = base[g];
    __syncthreads();

    for (int p=tid; p<14*TD; p+=256){
        int il = p / TD;
        int j  = p - il*TD;
        const float4* xj  = reinterpret_cast<const float4*>(g_xi + ((size_t)b*TD + j)*E8D);
        const float4* xi4 = reinterpret_cast<const float4*>(xs_i + il*E8D);
        float a0=0.f,a1=0.f,a2=0.f,a3=0.f;
#pragma unroll
        for (int q=0;q<16;q++){
            float4 u = xi4[q]; float4 v = xj[q];
            a0 += u.x*v.x; a1 += u.y*v.y; a2 += u.z*v.z; a3 += u.w*v.w;
        }
        sc[p] = (a0+a1+a2+a3) * (1.0f/512.0f);
    }
    __syncthreads();

    const int warp = tid >> 5, lane = tid & 31;
    for (int row = warp; row < 14; row += 8){
        float* r = sc + row*TD;
        float m = -1e30f;
        for (int j=lane;j<TD;j+=32) m = fmaxf(m, r[j]);
#pragma unroll
        for (int o=16;o>0;o>>=1) m = fmaxf(m, __shfl_xor_sync(0xffffffffu, m, o));
        float s = 0.f;
        for (int j=lane;j<TD;j+=32){ float v = __expf(r[j]-m); r[j]=v; s+=v; }
#pragma unroll
        for (int o=16;o>0;o>>=1) s += __shfl_xor_sync(0xffffffffu, s, o);
        float inv = 1.0f/s;
        float* dst = g_att + (size_t)b*TT + (size_t)(i0+row)*TD;
        for (int j=lane;j<TD;j+=32) dst[j] = r[j]*inv;
    }
}

// ============================================================
// Kernel 3: partial xt GEMM — C(16,392) += att(16,K) @ W_time^T(K,392)
// grid (NCHUNK, 2 r-halves), 128 threads, 8b x 4r reg tiles
// W_time read exactly once from DRAM (coalesced 128B rows)
// ============================================================
__global__ void k_xt(const float* __restrict__ Wt)
{
    __shared__ float As[16*33];    // 2.1 KB
    __shared__ float Ws[256*33];   // 33.8 KB
    const int c   = blockIdx.x;
    const int rh  = blockIdx.y;          // r half
    const int r_base = rh * 224;
    const int n_r = (rh==0) ? 224 : 168; // valid rows in this half
    const int tid = threadIdx.x;         // 128
    const int tr  = tid & 63;
    const int tbg = tid >> 6;            // 0/1 -> 8 b's each

    // zero padded rows so compute on r >= n_r is harmless
    for (int g = tid; g < (256-224)*33; g += 128) Ws[224*33 + g] = 0.f;
    if (rh == 1){
        for (int g = tid; g < (224-168)*33; g += 128) Ws[168*33 + g] = 0.f;
    }

    float acc[8][4];
#pragma unroll
    for (int i=0;i<8;i++)
#pragma unroll
        for (int j=0;j<4;j++) acc[i][j] = 0.f;

    const int s0 = c * SPB;
    const int s1 = min(s0 + SPB, KSTEPS_TOTAL);

    for (int s=s0; s<s1; s++){
        const int kb = s*32;
        __syncthreads();
        for (int g=tid; g<16*32; g+=128){
            int bb = g>>5, kk = g&31;
            As[bb*33+kk] = g_att[(size_t)bb*TT + kb + kk];
        }
        for (int g=tid; g<n_r*32; g+=128){
            int rr = g>>5, kk = g&31;
            Ws[rr*33+kk] = Wt[(size_t)(r_base+rr)*TT + kb + kk];
        }
        __syncthreads();
#pragma unroll
        for (int kk=0;kk<32;kk++){
            float a[8], w[4];
#pragma unroll
            for (int i=0;i<8;i++) a[i] = As[(tbg*8+i)*33+kk];
#pragma unroll
            for (int j=0;j<4;j++) w[j] = Ws[(tr+64*j)*33+kk];
#pragma unroll
            for (int i=0;i<8;i++)
#pragma unroll
                for (int j=0;j<4;j++) acc[i][j] += a[i]*w[j];
        }
    }

#pragma unroll
    for (int j=0;j<4;j++){
        int rl = tr + 64*j;
        if (rl < n_r){
            int r = r_base + rl;
#pragma unroll
            for (int i=0;i<8;i++)
                g_part[(size_t)c*(BB*TD) + (size_t)(tbg*8+i)*TD + r] = acc[i][j];
        }
    }
}

// deterministic reduction over the NCHUNK partials
__global__ void k_red(const float* __restrict__ bt)
{
    int idx = blockIdx.x*256 + threadIdx.x;
    if (idx >= BB*TD) return;
    float s = 0.f;
    for (int c=0;c<NCHUNK;c++) s += g_part[(size_t)c*(BB*TD) + idx];
    g_xt[idx] = s + bt[idx % TD];
}

// ============================================================
// Kernel 4: off = tanh(xt @ W_off^T)*2 -> sampling coords (i0,i1,w1)
// ============================================================
__global__ void k_off(const float* __restrict__ Wa,
                      const float* __restrict__ Wdd)
{
    __shared__ __align__(16) float xts[TD];
    const int b     = blockIdx.x;
    const int which = blockIdx.y;  // 0 = a, 1 = d
    const int tid   = threadIdx.x; // 224

    for (int g=tid; g<TD; g+=224) xts[g] = g_xt[b*TD + g];
    __syncthreads();

    if (tid < KD){
        const float* W = which ? Wdd : Wa;
        const float4* w4 = reinterpret_cast<const float4*>(W + (size_t)tid*TD);
        const float4* x4 = reinterpret_cast<const float4*>(xts);
        float a0=0.f,a1=0.f,a2=0.f,a3=0.f;
#pragma unroll 8
        for (int q=0;q<TD/4;q++){
            float4 u = x4[q]; float4 v = w4[q];
            a0 += u.x*v.x; a1 += u.y*v.y; a2 += u.z*v.z; a3 += u.w*v.w;
        }
        float off = tanhf(a0+a1+a2+a3) * 2.0f;                 // RECEPTIVE_FIELD
        float pos = 2.0f*(float)tid + (which ? 1.0f : 0.0f) + off;
        float g   = 2.0f*pos/391.0f - 1.0f;                    // normalize_grid, denom = T-1
        float ix  = ((g + 1.0f)*512.0f - 1.0f)*0.5f;           // unnormalize with c = C = 512
        float x0f = floorf(ix);
        float w1  = ix - x0f;
        int xi0 = (int)x0f;
        int i0 = min(max(xi0,     0), CD-1);
        int i1 = min(max(xi0 + 1, 0), CD-1);
        int o = which*(BB*KD) + b*KD + tid;
        g_i0[o] = i0; g_i1[o] = i1; g_w1[o] = w1;
    }
}

// ============================================================
// Kernel 5: out[which,b,t,k] = lerp(x[b,t,i0], x[b,t,i1], w1)
// ============================================================
__global__ void k_sample(const float* __restrict__ x,
                         float* __restrict__ out)
{
    __shared__ float xr[CD];
    const int bt  = blockIdx.x;
    const int b   = bt / TD;
    const int tid = threadIdx.x;  // 392

    const float* row = x + (size_t)bt*CD;
    for (int g=tid; g<CD; g+=392) xr[g] = row[g];
    __syncthreads();

    const int which = tid / KD;   // 0/1
    const int k     = tid - which*KD;
    const int o = which*(BB*KD) + b*KD + k;
    float w1 = g_w1[o];
    float v  = xr[g_i0[o]]*(1.0f - w1) + xr[g_i1[o]]*w1;
    out[(size_t)which*((size_t)BB*TD*KD) + (size_t)bt*KD + k] = v;
}

// ============================================================
extern "C" void kernel_launch(void* const* d_in, const int* in_sizes, int n_in,
                              void* d_out, int out_size)
{
    const float* x_in   = (const float*)d_in[0];
    const float* W_dim  = (const float*)d_in[1];
    const float* b_dim  = (const float*)d_in[2];
    const float* W_time = (const float*)d_in[3];
    const float* b_time = (const float*)d_in[4];
    const float* W_offa = (const float*)d_in[5];
    const float* W_offd = (const float*)d_in[6];
    float* out = (float*)d_out;

    k_xi    <<<dim3(13,16), 128>>>(x_in, W_dim, b_dim);
    k_att   <<<dim3(28,16), 256>>>();
    k_xt    <<<dim3(NCHUNK,2), 128>>>(W_time);
    k_red   <<<(BB*TD+255)/256, 256>>>(b_time);
    k_off   <<<dim3(16,2), 224>>>(W_offa, W_offd);
    k_sample<<<BB*TD, 392>>>(x_in, out);
}

// round 2
// speedup vs baseline: 1.1410x; 1.1410x over previous
#include <cuda_runtime.h>
#include <math.h>
#include <stdint.h>

#define BB 16
#define TD 392
#define CD 512
#define E8D 64
#define KD 196
#define TT (TD*TD)           // 153664
#define KSTEPS_TOTAL (TT/32) // 4802
#define NCHUNK 219
#define SPB 22               // ceil(4802/219)
#define RSLOT 256
#define SMEM_XT ((2*512 + 2*RSLOT*32)*4)  // 69632 B

// ---- scratch (device globals; no allocation allowed) ----
__device__ __align__(16) float g_xi [BB*TD*E8D];       // 1.6 MB
__device__ __align__(16) float g_att[BB*TT];           // 9.8 MB
__device__ __align__(16) float g_part[NCHUNK*BB*TD];   // 5.5 MB
__device__ __align__(16) float g_xt [BB*TD];
__device__ int   g_i0[2*BB*KD];
__device__ int   g_i1[2*BB*KD];
__device__ float g_w1[2*BB*KD];

// ---- helpers ----
__device__ __forceinline__ uint32_t smem_u32(const void* p){
    uint32_t a;
    asm("{ .reg .u64 t; cvta.to.shared.u64 t, %1; cvt.u32.u64 %0, t; }" : "=r"(a) : "l"(p));
    return a;
}
__device__ __forceinline__ void cp16(uint32_t dst, const void* src){
    asm volatile("cp.async.cg.shared.global [%0], [%1], 16;" :: "r"(dst), "l"(src));
}
__device__ __forceinline__ void cp8(uint32_t dst, const void* src){
    asm volatile("cp.async.ca.shared.global [%0], [%1], 8;" :: "r"(dst), "l"(src));
}
__device__ __forceinline__ void fma2(unsigned long long& d, unsigned long long a, unsigned long long b){
    asm("fma.rn.f32x2 %0, %1, %2, %0;" : "+l"(d) : "l"(a), "l"(b));
}

// ============================================================
// Kernel 1: xi[b,t,e] = x[b,t,:] . W_dim[e,:] + b_dim[e]
// ============================================================
__global__ void k_xi(const float* __restrict__ x,
                     const float* __restrict__ Wd,
                     const float* __restrict__ bd)
{
    __shared__ float xs[32*33];
    __shared__ float ws[64*33];
    const int b  = blockIdx.y;
    const int t0 = blockIdx.x * 32;
    const int tid = threadIdx.x;
    const int tx = tid & 15;
    const int ty = tid >> 4;

    float acc[4][4];
#pragma unroll
    for (int j=0;j<4;j++)
#pragma unroll
        for (int i=0;i<4;i++) acc[j][i] = 0.f;

    for (int s=0; s<CD/32; s++){
        const int k0 = s*32;
        __syncthreads();
        for (int g=tid; g<32*32; g+=128){
            int tt = g>>5, kk = g&31;
            int t = t0+tt;
            xs[tt*33+kk] = (t<TD) ? x[((size_t)b*TD+t)*CD + k0+kk] : 0.f;
        }
        for (int g=tid; g<64*32; g+=128){
            int ee = g>>5, kk = g&31;
            ws[ee*33+kk] = Wd[ee*CD + k0+kk];
        }
        __syncthreads();
#pragma unroll
        for (int kk=0;kk<32;kk++){
            float xv[4], wv[4];
#pragma unroll
            for (int j=0;j<4;j++) xv[j] = xs[(ty+8*j)*33+kk];
#pragma unroll
            for (int i=0;i<4;i++) wv[i] = ws[(tx+16*i)*33+kk];
#pragma unroll
            for (int j=0;j<4;j++)
#pragma unroll
                for (int i=0;i<4;i++) acc[j][i] += xv[j]*wv[i];
        }
    }
#pragma unroll
    for (int j=0;j<4;j++){
        int t = t0 + ty + 8*j;
        if (t < TD){
#pragma unroll
            for (int i=0;i<4;i++){
                int e = tx + 16*i;
                g_xi[((size_t)b*TD+t)*E8D + e] = acc[j][i] + bd[e];
            }
        }
    }
}

// ============================================================
// Kernel 2: att[b,i,:] = softmax_j( xi_i . xi_j / 512 )
// ============================================================
__global__ void k_att()
{
    __shared__ __align__(16) float xs_i[14*E8D];
    __shared__ float sc[14*TD];
    const int b  = blockIdx.y;
    const int i0 = blockIdx.x * 14;
    const int tid = threadIdx.x;   // 256

    const float* base = g_xi + ((size_t)b*TD + i0)*E8D;
    for (int g=tid; g<14*E8D; g+=256) xs_i[g] = base[g];
    __syncthreads();

    for (int p=tid; p<14*TD; p+=256){
        int il = p / TD;
        int j  = p - il*TD;
        const float4* xj  = reinterpret_cast<const float4*>(g_xi + ((size_t)b*TD + j)*E8D);
        const float4* xi4 = reinterpret_cast<const float4*>(xs_i + il*E8D);
        float a0=0.f,a1=0.f,a2=0.f,a3=0.f;
#pragma unroll
        for (int q=0;q<16;q++){
            float4 u = xi4[q]; float4 v = xj[q];
            a0 += u.x*v.x; a1 += u.y*v.y; a2 += u.z*v.z; a3 += u.w*v.w;
        }
        sc[p] = (a0+a1+a2+a3) * (1.0f/512.0f);
    }
    __syncthreads();

    const int warp = tid >> 5, lane = tid & 31;
    for (int row = warp; row < 14; row += 8){
        float* r = sc + row*TD;
        float m = -1e30f;
        for (int j=lane;j<TD;j+=32) m = fmaxf(m, r[j]);
#pragma unroll
        for (int o=16;o>0;o>>=1) m = fmaxf(m, __shfl_xor_sync(0xffffffffu, m, o));
        float s = 0.f;
        for (int j=lane;j<TD;j+=32){ float v = __expf(r[j]-m); r[j]=v; s+=v; }
#pragma unroll
        for (int o=16;o>0;o>>=1) s += __shfl_xor_sync(0xffffffffu, s, o);
        float inv = 1.0f/s;
        float* dst = g_att + (size_t)b*TT + (size_t)(i0+row)*TD;
        for (int j=lane;j<TD;j+=32) dst[j] = r[j]*inv;
    }
}

// ============================================================
// Kernel 3: partial xt GEMM — cp.async double-buffered + f32x2
// C(16,392) partials over 219 K-chunks.
// Ws smem layout: [r][16 float2], float2 col swizzled by (kk2 ^ (r&15)).
// ============================================================
__global__ void __launch_bounds__(128) k_xt(const float* __restrict__ Wt)
{
    extern __shared__ float sm[];
    float* As = sm;                 // 2 bufs x 512 floats
    float* Ws = sm + 1024;          // 2 bufs x 8192 floats
    const uint32_t as_base = smem_u32(As);
    const uint32_t ws_base = smem_u32(Ws);

    const int c   = blockIdx.x;
    const int rh  = blockIdx.y;
    const int r_base = rh * 224;
    const int n_r = (rh==0) ? 224 : 168;
    const int tid = threadIdx.x;    // 128
    const int tr  = tid & 63;
    const int tbg = tid >> 6;

    // zero pad rows (both buffers) so compute on r >= n_r is harmless
    {
        int padElems = (RSLOT - n_r)*32;
        for (int g=tid; g<padElems; g+=128){
            Ws[n_r*32 + g] = 0.f;
            Ws[8192 + n_r*32 + g] = 0.f;
        }
    }

    unsigned long long acc[8][4];
#pragma unroll
    for (int i=0;i<8;i++)
#pragma unroll
        for (int j=0;j<4;j++) acc[i][j] = 0ull;

    const int s0 = c * SPB;
    const int s1 = min(s0 + SPB, KSTEPS_TOTAL);

    // per-thread row constants for compute
    int rl[4]; uint32_t wrow[4];
#pragma unroll
    for (int j=0;j<4;j++){ rl[j] = tr + 64*j; }

    if (s0 < s1){
        // ---- stage s0 into buf 0 ----
        {
            const int kb = s0*32;
            int bb = tid >> 3, c4 = tid & 7;
            cp16(as_base + (uint32_t)(bb*32 + c4*4)*4u,
                 g_att + (size_t)bb*TT + kb + c4*4);
            for (int u = tid; u < n_r*16; u += 128){
                int r = u >> 4, c2 = u & 15;
                int c2s = c2 ^ (r & 15);
                cp8(ws_base + (uint32_t)(r*32 + c2s*2)*4u,
                    Wt + (size_t)(r_base+r)*TT + kb + c2*2);
            }
            asm volatile("cp.async.commit_group;" ::: "memory");
        }

        for (int s = s0; s < s1; s++){
            const int buf = (s - s0) & 1;
            const bool more = (s+1 < s1);
            if (more){
                const int kb = (s+1)*32;
                const uint32_t abuf = as_base + (uint32_t)(buf^1)*512u*4u;
                const uint32_t wbuf = ws_base + (uint32_t)(buf^1)*8192u*4u;
                int bb = tid >> 3, c4 = tid & 7;
                cp16(abuf + (uint32_t)(bb*32 + c4*4)*4u,
                     g_att + (size_t)bb*TT + kb + c4*4);
                for (int u = tid; u < n_r*16; u += 128){
                    int r = u >> 4, c2 = u & 15;
                    int c2s = c2 ^ (r & 15);
                    cp8(wbuf + (uint32_t)(r*32 + c2s*2)*4u,
                        Wt + (size_t)(r_base+r)*TT + kb + c2*2);
                }
                asm volatile("cp.async.commit_group;" ::: "memory");
                asm volatile("cp.async.wait_group 1;" ::: "memory");
            } else {
                asm volatile("cp.async.wait_group 0;" ::: "memory");
            }
            __syncthreads();

            const float* A = As + buf*512 + tbg*8*32;
            const float* W = Ws + buf*8192;
#pragma unroll
            for (int kk2=0; kk2<16; kk2++){
                unsigned long long a2[8], w2[4];
#pragma unroll
                for (int i=0;i<8;i++)
                    a2[i] = *reinterpret_cast<const unsigned long long*>(A + i*32 + kk2*2);
#pragma unroll
                for (int j=0;j<4;j++)
                    w2[j] = *reinterpret_cast<const unsigned long long*>(
                               W + rl[j]*32 + ((kk2 ^ (rl[j]&15))<<1));
#pragma unroll
                for (int i=0;i<8;i++)
#pragma unroll
                    for (int j=0;j<4;j++) fma2(acc[i][j], a2[i], w2[j]);
            }
            __syncthreads();
        }
    }

    // epilogue: fold pair halves, write partials (coalesced over r)
#pragma unroll
    for (int j=0;j<4;j++){
        if (rl[j] < n_r){
            int r = r_base + rl[j];
#pragma unroll
            for (int i=0;i<8;i++){
                float2 v = *reinterpret_cast<float2*>(&acc[i][j]);
                g_part[(size_t)c*(BB*TD) + (size_t)(tbg*8+i)*TD + r] = v.x + v.y;
            }
        }
    }
}

// deterministic reduction: 196 blocks x 256 thr, 8 c-lanes x 32 outputs
__global__ void k_red(const float* __restrict__ bt)
{
    const int out0 = blockIdx.x * 32;
    const int lane8 = threadIdx.x & 7;
    const int o = threadIdx.x >> 3;
    const int idx = out0 + o;
    float s = 0.f;
#pragma unroll 4
    for (int c = lane8; c < NCHUNK; c += 8)
        s += g_part[(size_t)c*(BB*TD) + idx];
#pragma unroll
    for (int off=1; off<8; off<<=1) s += __shfl_xor_sync(0xffffffffu, s, off);
    if (lane8 == 0) g_xt[idx] = s + bt[idx % TD];
}

// ============================================================
// Kernel 4: off = tanh(xt @ W_off^T)*2 -> sampling coords
// ============================================================
__global__ void k_off(const float* __restrict__ Wa,
                      const float* __restrict__ Wdd)
{
    __shared__ __align__(16) float xts[TD];
    const int b     = blockIdx.x;
    const int which = blockIdx.y;
    const int tid   = threadIdx.x; // 224

    for (int g=tid; g<TD; g+=224) xts[g] = g_xt[b*TD + g];
    __syncthreads();

    if (tid < KD){
        const float* W = which ? Wdd : Wa;
        const float4* w4 = reinterpret_cast<const float4*>(W + (size_t)tid*TD);
        const float4* x4 = reinterpret_cast<const float4*>(xts);
        float a0=0.f,a1=0.f,a2=0.f,a3=0.f;
#pragma unroll 8
        for (int q=0;q<TD/4;q++){
            float4 u = x4[q]; float4 v = w4[q];
            a0 += u.x*v.x; a1 += u.y*v.y; a2 += u.z*v.z; a3 += u.w*v.w;
        }
        float off = tanhf(a0+a1+a2+a3) * 2.0f;
        float pos = 2.0f*(float)tid + (which ? 1.0f : 0.0f) + off;
        float g   = 2.0f*pos/391.0f - 1.0f;
        float ix  = ((g + 1.0f)*512.0f - 1.0f)*0.5f;
        float x0f = floorf(ix);
        float w1  = ix - x0f;
        int xi0 = (int)x0f;
        int i0 = min(max(xi0,     0), CD-1);
        int i1 = min(max(xi0 + 1, 0), CD-1);
        int o = which*(BB*KD) + b*KD + tid;
        g_i0[o] = i0; g_i1[o] = i1; g_w1[o] = w1;
    }
}

// ============================================================
// Kernel 5: out[which,b,t,k] = lerp(x[b,t,i0], x[b,t,i1], w1)
// ============================================================
__global__ void k_sample(const float* __restrict__ x,
                         float* __restrict__ out)
{
    __shared__ float xr[CD];
    const int bt  = blockIdx.x;
    const int b   = bt / TD;
    const int tid = threadIdx.x;  // 392

    const float* row = x + (size_t)bt*CD;
    for (int g=tid; g<CD; g+=392) xr[g] = row[g];
    __syncthreads();

    const int which = tid / KD;
    const int k     = tid - which*KD;
    const int o = which*(BB*KD) + b*KD + k;
    float w1 = g_w1[o];
    float v  = xr[g_i0[o]]*(1.0f - w1) + xr[g_i1[o]]*w1;
    out[(size_t)which*((size_t)BB*TD*KD) + (size_t)bt*KD + k] = v;
}

// ============================================================
extern "C" void kernel_launch(void* const* d_in, const int* in_sizes, int n_in,
                              void* d_out, int out_size)
{
    const float* x_in   = (const float*)d_in[0];
    const float* W_dim  = (const float*)d_in[1];
    const float* b_dim  = (const float*)d_in[2];
    const float* W_time = (const float*)d_in[3];
    const float* b_time = (const float*)d_in[4];
    const float* W_offa = (const float*)d_in[5];
    const float* W_offd = (const float*)d_in[6];
    float* out = (float*)d_out;

    cudaFuncSetAttribute(k_xt, cudaFuncAttributeMaxDynamicSharedMemorySize, SMEM_XT);

    k_xi    <<<dim3(13,16), 128>>>(x_in, W_dim, b_dim);
    k_att   <<<dim3(28,16), 256>>>();
    k_xt    <<<dim3(NCHUNK,2), 128, SMEM_XT>>>(W_time);
    k_red   <<<196, 256>>>(b_time);
    k_off   <<<dim3(16,2), 224>>>(W_offa, W_offd);
    k_sample<<<BB*TD, 392>>>(x_in, out);
}